// round 14
// baseline (speedup 1.0000x reference)
#include <cuda_runtime.h>
#include <cuda_fp16.h>
#include <cstdint>

#define OUTD 11008
#define IND  4096
#define BDIM 8192
#define NELEM (OUTD * IND)
#define PPACK (NELEM / 2)
#define XELEM (BDIM * IND)

__device__ __half g_W[NELEM];
__device__ __half g_X[XELEM];

// ---------------------------------------------------------------------------
// Kernel P: fused prep. Blocks [0, XBLK) convert x f32->fp16; the rest
// dequantize packed 4-bit -> fp16 W.
// ---------------------------------------------------------------------------
#define XBLK (XELEM / 8 / 256)        // 16384
#define DQBLK (PPACK / 8 / 256)       // 11008

__global__ void __launch_bounds__(256) prep_kernel(
    const float* __restrict__ x,
    const int*   __restrict__ packed,
    const int*   __restrict__ absmax1,
    const float* __restrict__ code1,
    const float* __restrict__ offset1,
    const float* __restrict__ absmax2,
    const float* __restrict__ code2)
{
    if (blockIdx.x < XBLK) {
        int tid = blockIdx.x * 256 + threadIdx.x;
        const float4* x4 = (const float4*)x;
        float4 a = x4[tid * 2];
        float4 b = x4[tid * 2 + 1];
        __half h[8];
        h[0] = __float2half(a.x); h[1] = __float2half(a.y);
        h[2] = __float2half(a.z); h[3] = __float2half(a.w);
        h[4] = __float2half(b.x); h[5] = __float2half(b.y);
        h[6] = __float2half(b.z); h[7] = __float2half(b.w);
        ((uint4*)g_X)[tid] = *(const uint4*)h;
    } else {
        int tid = (blockIdx.x - XBLK) * 256 + threadIdx.x;   // [0, PPACK/8)
        int blk1 = tid >> 2;
        int blk2 = tid >> 4;
        float s   = ((float)absmax1[blk1] / code1[blk1]) * (absmax2[blk2] / code2[blk2]);
        float off = offset1[blk1];
        const int4* p4 = (const int4*)packed;
        int4 p0 = p4[tid * 2];
        int4 p1 = p4[tid * 2 + 1];
        int b[8] = {p0.x, p0.y, p0.z, p0.w, p1.x, p1.y, p1.z, p1.w};
        __half h[16];
#pragma unroll
        for (int j = 0; j < 8; j++) {
            float lo = (float)(b[j] & 15);
            float hi = (float)((b[j] >> 4) & 15);
            h[2 * j]     = __float2half((lo - off) * s);
            h[2 * j + 1] = __float2half((hi - off) * s);
        }
        uint4* w4 = (uint4*)g_W;
        const uint4* hv = (const uint4*)h;
        w4[tid * 2]     = hv[0];
        w4[tid * 2 + 1] = hv[1];
    }
}

// ---------------------------------------------------------------------------
// Kernel 2: HMMA GEMM — persistent CTAs with a CONTINUOUS cross-tile load
// stream (next tile's prologue prefetched during current tile's tail).
// BM=128, BN=128, BK=64; 8 warps 4(M)x2(N); 3-stage ring; 2 CTAs/SM.
// Tile order: bm = t & 63 (fast), bn = t >> 6  (X L2-resident, W streams).
// ---------------------------------------------------------------------------
#define BM 128
#define BN 128
#define BK 64
#define STAGES 3
#define KTILES (IND / BK)            // 64
#define STG_BYTES 16384
#define SMEM_TOTAL (2 * STAGES * STG_BYTES)   // 98304
#define NTILES ((OUTD / BN) * (BDIM / BM))    // 86*64 = 5504
#define NPERSIST 296                          // 148 SMs x 2 CTAs

__device__ __forceinline__ unsigned swz(int row, int kc) {
    return (unsigned)(row * 128 + ((kc ^ (row & 7)) << 4));
}
__device__ __forceinline__ void ldm_x4(unsigned* d, unsigned addr) {
    asm volatile("ldmatrix.sync.aligned.m8n8.x4.shared.b16 {%0,%1,%2,%3}, [%4];"
                 : "=r"(d[0]), "=r"(d[1]), "=r"(d[2]), "=r"(d[3]) : "r"(addr));
}
__device__ __forceinline__ void mma16816(float* c, const unsigned* a,
                                         unsigned b0, unsigned b1) {
    asm volatile(
        "mma.sync.aligned.m16n8k16.row.col.f32.f16.f16.f32 "
        "{%0,%1,%2,%3}, {%4,%5,%6,%7}, {%8,%9}, {%0,%1,%2,%3};"
        : "+f"(c[0]), "+f"(c[1]), "+f"(c[2]), "+f"(c[3])
        : "r"(a[0]), "r"(a[1]), "r"(a[2]), "r"(a[3]), "r"(b0), "r"(b1));
}
__device__ __forceinline__ void cp_async16(unsigned saddr, const void* gaddr) {
    asm volatile("cp.async.cg.shared.global [%0], [%1], 16;"
                 :: "r"(saddr), "l"(gaddr));
}
__device__ __forceinline__ void stcs2(float* p, float a, float b) {
    asm volatile("st.global.cs.v2.f32 [%0], {%1, %2};" :: "l"(p), "f"(a), "f"(b)
                 : "memory");
}

__global__ void __launch_bounds__(256, 2) gemm_kernel(float* __restrict__ C)
{
    extern __shared__ char smem[];
    unsigned sA = (unsigned)__cvta_generic_to_shared(smem);
    unsigned sB = sA + STAGES * STG_BYTES;

    const int tid  = threadIdx.x;
    const int lane = tid & 31;
    const int warp = tid >> 5;
    const int wm   = warp >> 1;     // 0..3
    const int wn   = warp & 1;      // 0..1

    const int rselA = lane & 15;
    const int cselA = lane >> 4;
    const int rselB = (lane & 7) | ((lane >> 1) & 8);
    const int cselB = (lane >> 3) & 1;

    unsigned aRowOff[2]; int aXor[2];
#pragma unroll
    for (int mi = 0; mi < 2; mi++) {
        int r = wm * 32 + mi * 16 + rselA;
        aRowOff[mi] = (unsigned)(r * 128);
        aXor[mi] = r & 7;
    }
    unsigned bRowOff[4]; int bXor[4];
#pragma unroll
    for (int nj = 0; nj < 4; nj++) {
        int r = wn * 64 + nj * 16 + rselB;
        bRowOff[nj] = (unsigned)(r * 128);
        bXor[nj] = r & 7;
    }

    // per-thread cp.async coords (loop-invariant)
    int ldRow[4], ldKc[4];
#pragma unroll
    for (int i = 0; i < 4; i++) {
        int id = tid + i * 256;
        ldRow[i] = id >> 3;
        ldKc[i]  = id & 7;
    }

    // ---- continuous load stream state ----
    int load_t  = blockIdx.x;
    int load_kt = 0;
    unsigned lslot = 0;
    const __half* lx = g_X + (size_t)(load_t & 63) * BM * IND;
    const __half* lw = g_W + (size_t)(load_t >> 6) * BN * IND;

    auto issue_load = [&]() {
        if (load_t < NTILES) {
            unsigned aB = sA + lslot * STG_BYTES;
            unsigned bB = sB + lslot * STG_BYTES;
            const __half* xs = lx + (size_t)load_kt * BK;
            const __half* ws = lw + (size_t)load_kt * BK;
#pragma unroll
            for (int i = 0; i < 4; i++)
                cp_async16(aB + swz(ldRow[i], ldKc[i]),
                           xs + (size_t)ldRow[i] * IND + ldKc[i] * 8);
#pragma unroll
            for (int i = 0; i < 4; i++)
                cp_async16(bB + swz(ldRow[i], ldKc[i]),
                           ws + (size_t)ldRow[i] * IND + ldKc[i] * 8);
        }
        asm volatile("cp.async.commit_group;");
        lslot = (lslot == STAGES - 1) ? 0 : lslot + 1;
        if (++load_kt == KTILES) {
            load_kt = 0;
            load_t += NPERSIST;
            if (load_t < NTILES) {
                lx = g_X + (size_t)(load_t & 63) * BM * IND;
                lw = g_W + (size_t)(load_t >> 6) * BN * IND;
            }
        }
    };

    // prime 2 stages (global iterations 0,1)
    issue_load();
    issue_load();

    unsigned cslot = 0;
    for (int t = blockIdx.x; t < NTILES; t += NPERSIST) {
        float acc[2][8][4] = {};

        for (int kt = 0; kt < KTILES; kt++) {
            asm volatile("cp.async.wait_group 1;");   // iteration g resident
            __syncthreads();                          // all warps done with g-1

            issue_load();                             // iteration g+2 (may be next tile)

            unsigned aBase = sA + cslot * STG_BYTES;
            unsigned bBase = sB + cslot * STG_BYTES;
            cslot = (cslot == STAGES - 1) ? 0 : cslot + 1;
#pragma unroll
            for (int kk = 0; kk < 4; kk++) {
                unsigned afrag[2][4];
#pragma unroll
                for (int mi = 0; mi < 2; mi++) {
                    int kc = kk * 2 + cselA;
                    ldm_x4(afrag[mi], aBase + aRowOff[mi] + (unsigned)((kc ^ aXor[mi]) << 4));
                }
                unsigned bfrag[4][4];
#pragma unroll
                for (int nj = 0; nj < 4; nj++) {
                    int kc = kk * 2 + cselB;
                    ldm_x4(bfrag[nj], bBase + bRowOff[nj] + (unsigned)((kc ^ bXor[nj]) << 4));
                }
#pragma unroll
                for (int mi = 0; mi < 2; mi++) {
#pragma unroll
                    for (int nj = 0; nj < 4; nj++) {
                        mma16816(acc[mi][2 * nj],     afrag[mi], bfrag[nj][0], bfrag[nj][1]);
                        mma16816(acc[mi][2 * nj + 1], afrag[mi], bfrag[nj][2], bfrag[nj][3]);
                    }
                }
            }
        }

        // ---- epilogue (registers only; next tile's loads already in flight) ----
        const int bm = t & 63;
        const int bn = t >> 6;
        const int r0 = bm * BM + wm * 32 + (lane >> 2);
        const int c0 = bn * BN + wn * 64 + 2 * (lane & 3);
#pragma unroll
        for (int mi = 0; mi < 2; mi++) {
#pragma unroll
            for (int ni = 0; ni < 8; ni++) {
                int r = r0 + mi * 16;
                int c = c0 + ni * 8;
                stcs2(C + (size_t)r * OUTD + c,
                      __half2float(__float2half(acc[mi][ni][0])),
                      __half2float(__float2half(acc[mi][ni][1])));
                stcs2(C + (size_t)(r + 8) * OUTD + c,
                      __half2float(__float2half(acc[mi][ni][2])),
                      __half2float(__float2half(acc[mi][ni][3])));
            }
        }
    }
}

// ---------------------------------------------------------------------------
extern "C" void kernel_launch(void* const* d_in, const int* in_sizes, int n_in,
                              void* d_out, int out_size)
{
    const float* x      = (const float*)d_in[0];
    const int*   packed = (const int*)  d_in[1];
    const int*   am1    = (const int*)  d_in[2];
    const float* c1     = (const float*)d_in[3];
    const float* o1     = (const float*)d_in[4];
    const float* am2    = (const float*)d_in[5];
    const float* c2     = (const float*)d_in[6];
    float* out = (float*)d_out;

    prep_kernel<<<XBLK + DQBLK, 256>>>(x, packed, am1, c1, o1, am2, c2);

    cudaFuncSetAttribute(gemm_kernel,
                         cudaFuncAttributeMaxDynamicSharedMemorySize, SMEM_TOTAL);
    gemm_kernel<<<NPERSIST, 256, SMEM_TOTAL>>>(out);
}

// round 15
// speedup vs baseline: 1.0145x; 1.0145x over previous
#include <cuda_runtime.h>
#include <cuda_fp16.h>
#include <cstdint>

#define OUTD 11008
#define IND  4096
#define BDIM 8192
#define NELEM (OUTD * IND)
#define PPACK (NELEM / 2)
#define XELEM (BDIM * IND)

__device__ __half g_W[NELEM];
__device__ __half g_X[XELEM];

// ---------------------------------------------------------------------------
// Kernel P: fused prep. Blocks [0, XBLK) convert x f32->fp16; the rest
// dequantize packed 4-bit -> fp16 W. Both HBM-bound; one grid keeps HBM full.
// ---------------------------------------------------------------------------
#define XBLK (XELEM / 8 / 256)        // 16384
#define DQBLK (PPACK / 8 / 256)       // 11008

__global__ void __launch_bounds__(256) prep_kernel(
    const float* __restrict__ x,
    const int*   __restrict__ packed,
    const int*   __restrict__ absmax1,
    const float* __restrict__ code1,
    const float* __restrict__ offset1,
    const float* __restrict__ absmax2,
    const float* __restrict__ code2)
{
    if (blockIdx.x < XBLK) {
        int tid = blockIdx.x * 256 + threadIdx.x;
        const float4* x4 = (const float4*)x;
        float4 a = x4[tid * 2];
        float4 b = x4[tid * 2 + 1];
        __half h[8];
        h[0] = __float2half(a.x); h[1] = __float2half(a.y);
        h[2] = __float2half(a.z); h[3] = __float2half(a.w);
        h[4] = __float2half(b.x); h[5] = __float2half(b.y);
        h[6] = __float2half(b.z); h[7] = __float2half(b.w);
        ((uint4*)g_X)[tid] = *(const uint4*)h;
    } else {
        int tid = (blockIdx.x - XBLK) * 256 + threadIdx.x;   // [0, PPACK/8)
        int blk1 = tid >> 2;
        int blk2 = tid >> 4;
        float s   = ((float)absmax1[blk1] / code1[blk1]) * (absmax2[blk2] / code2[blk2]);
        float off = offset1[blk1];
        const int4* p4 = (const int4*)packed;
        int4 p0 = p4[tid * 2];
        int4 p1 = p4[tid * 2 + 1];
        int b[8] = {p0.x, p0.y, p0.z, p0.w, p1.x, p1.y, p1.z, p1.w};
        __half h[16];
#pragma unroll
        for (int j = 0; j < 8; j++) {
            float lo = (float)(b[j] & 15);
            float hi = (float)((b[j] >> 4) & 15);
            h[2 * j]     = __float2half((lo - off) * s);
            h[2 * j + 1] = __float2half((hi - off) * s);
        }
        uint4* w4 = (uint4*)g_W;
        const uint4* hv = (const uint4*)h;
        w4[tid * 2]     = hv[0];
        w4[tid * 2 + 1] = hv[1];
    }
}

// ---------------------------------------------------------------------------
// Kernel 2: HMMA GEMM — R5 mainloop (measured best operating point).
// BM=128, BN=128, BK=64; 8 warps 4(M)x2(N), warp tile 32x64; 3-stage ring;
// 2 CTAs/SM. Epilogue uses streaming stores (evict-first) to preserve L2.
// ---------------------------------------------------------------------------
#define BM 128
#define BN 128
#define BK 64
#define STAGES 3
#define KTILES (IND / BK)            // 64
#define STG_BYTES 16384
#define SMEM_TOTAL (2 * STAGES * STG_BYTES)   // 98304

__device__ __forceinline__ unsigned swz(int row, int kc) {
    return (unsigned)(row * 128 + ((kc ^ (row & 7)) << 4));
}
__device__ __forceinline__ void ldm_x4(unsigned* d, unsigned addr) {
    asm volatile("ldmatrix.sync.aligned.m8n8.x4.shared.b16 {%0,%1,%2,%3}, [%4];"
                 : "=r"(d[0]), "=r"(d[1]), "=r"(d[2]), "=r"(d[3]) : "r"(addr));
}
__device__ __forceinline__ void mma16816(float* c, const unsigned* a,
                                         unsigned b0, unsigned b1) {
    asm volatile(
        "mma.sync.aligned.m16n8k16.row.col.f32.f16.f16.f32 "
        "{%0,%1,%2,%3}, {%4,%5,%6,%7}, {%8,%9}, {%0,%1,%2,%3};"
        : "+f"(c[0]), "+f"(c[1]), "+f"(c[2]), "+f"(c[3])
        : "r"(a[0]), "r"(a[1]), "r"(a[2]), "r"(a[3]), "r"(b0), "r"(b1));
}
__device__ __forceinline__ void cp_async16(unsigned saddr, const void* gaddr) {
    asm volatile("cp.async.cg.shared.global [%0], [%1], 16;"
                 :: "r"(saddr), "l"(gaddr));
}
__device__ __forceinline__ void stcs2(float* p, float a, float b) {
    asm volatile("st.global.cs.v2.f32 [%0], {%1, %2};" :: "l"(p), "f"(a), "f"(b)
                 : "memory");
}

__global__ void __launch_bounds__(256, 2) gemm_kernel(float* __restrict__ C)
{
    extern __shared__ char smem[];
    unsigned sA = (unsigned)__cvta_generic_to_shared(smem);
    unsigned sB = sA + STAGES * STG_BYTES;

    const int tid  = threadIdx.x;
    const int lane = tid & 31;
    const int warp = tid >> 5;
    const int wm   = warp >> 1;     // 0..3
    const int wn   = warp & 1;      // 0..1

    const int bn = blockIdx.x;
    const int bm = blockIdx.y;

    const __half* xsrc0 = g_X + (size_t)bm * BM * IND;
    const __half* wsrc0 = g_W + (size_t)bn * BN * IND;

    float acc[2][8][4] = {};

    const int rselA = lane & 15;
    const int cselA = lane >> 4;
    const int rselB = (lane & 7) | ((lane >> 1) & 8);
    const int cselB = (lane >> 3) & 1;

    unsigned aRowOff[2]; int aXor[2];
#pragma unroll
    for (int mi = 0; mi < 2; mi++) {
        int r = wm * 32 + mi * 16 + rselA;
        aRowOff[mi] = (unsigned)(r * 128);
        aXor[mi] = r & 7;
    }
    unsigned bRowOff[4]; int bXor[4];
#pragma unroll
    for (int nj = 0; nj < 4; nj++) {
        int r = wn * 64 + nj * 16 + rselB;
        bRowOff[nj] = (unsigned)(r * 128);
        bXor[nj] = r & 7;
    }

    auto load_stage = [&](int slot, int kt) {
        unsigned aB = sA + slot * STG_BYTES;
        unsigned bB = sB + slot * STG_BYTES;
        const __half* xs = xsrc0 + (size_t)kt * BK;
        const __half* ws = wsrc0 + (size_t)kt * BK;
#pragma unroll
        for (int i = 0; i < 4; i++) {
            int id = tid + i * 256;
            int row = id >> 3, kc = id & 7;
            cp_async16(aB + swz(row, kc), xs + (size_t)row * IND + kc * 8);
        }
#pragma unroll
        for (int i = 0; i < 4; i++) {
            int id = tid + i * 256;
            int row = id >> 3, kc = id & 7;
            cp_async16(bB + swz(row, kc), ws + (size_t)row * IND + kc * 8);
        }
    };

    load_stage(0, 0);
    asm volatile("cp.async.commit_group;");
    load_stage(1, 1);
    asm volatile("cp.async.commit_group;");

    for (int kt = 0; kt < KTILES; kt++) {
        asm volatile("cp.async.wait_group 1;");   // stage kt resident
        __syncthreads();                          // all warps done with kt-1

        if (kt + 2 < KTILES) load_stage((kt + 2) % STAGES, kt + 2);
        asm volatile("cp.async.commit_group;");

        unsigned aBase = sA + (kt % STAGES) * STG_BYTES;
        unsigned bBase = sB + (kt % STAGES) * STG_BYTES;
#pragma unroll
        for (int kk = 0; kk < 4; kk++) {
            unsigned afrag[2][4];
#pragma unroll
            for (int mi = 0; mi < 2; mi++) {
                int kc = kk * 2 + cselA;
                ldm_x4(afrag[mi], aBase + aRowOff[mi] + (unsigned)((kc ^ aXor[mi]) << 4));
            }
            unsigned bfrag[4][4];
#pragma unroll
            for (int nj = 0; nj < 4; nj++) {
                int kc = kk * 2 + cselB;
                ldm_x4(bfrag[nj], bBase + bRowOff[nj] + (unsigned)((kc ^ bXor[nj]) << 4));
            }
#pragma unroll
            for (int mi = 0; mi < 2; mi++) {
#pragma unroll
                for (int nj = 0; nj < 4; nj++) {
                    mma16816(acc[mi][2 * nj],     afrag[mi], bfrag[nj][0], bfrag[nj][1]);
                    mma16816(acc[mi][2 * nj + 1], afrag[mi], bfrag[nj][2], bfrag[nj][3]);
                }
            }
        }
    }

    // ---- epilogue: fp16-round, streaming f32 stores (evict-first) ----
    const int r0 = bm * BM + wm * 32 + (lane >> 2);
    const int c0 = bn * BN + wn * 64 + 2 * (lane & 3);
#pragma unroll
    for (int mi = 0; mi < 2; mi++) {
#pragma unroll
        for (int ni = 0; ni < 8; ni++) {
            int r = r0 + mi * 16;
            int c = c0 + ni * 8;
            stcs2(C + (size_t)r * OUTD + c,
                  __half2float(__float2half(acc[mi][ni][0])),
                  __half2float(__float2half(acc[mi][ni][1])));
            stcs2(C + (size_t)(r + 8) * OUTD + c,
                  __half2float(__float2half(acc[mi][ni][2])),
                  __half2float(__float2half(acc[mi][ni][3])));
        }
    }
}

// ---------------------------------------------------------------------------
extern "C" void kernel_launch(void* const* d_in, const int* in_sizes, int n_in,
                              void* d_out, int out_size)
{
    const float* x      = (const float*)d_in[0];
    const int*   packed = (const int*)  d_in[1];
    const int*   am1    = (const int*)  d_in[2];
    const float* c1     = (const float*)d_in[3];
    const float* o1     = (const float*)d_in[4];
    const float* am2    = (const float*)d_in[5];
    const float* c2     = (const float*)d_in[6];
    float* out = (float*)d_out;

    prep_kernel<<<XBLK + DQBLK, 256>>>(x, packed, am1, c1, o1, am2, c2);

    cudaFuncSetAttribute(gemm_kernel,
                         cudaFuncAttributeMaxDynamicSharedMemorySize, SMEM_TOTAL);
    gemm_kernel<<<dim3(OUTD / BN, BDIM / BM), 256, SMEM_TOTAL>>>(out);
}

// round 16
// speedup vs baseline: 1.0754x; 1.0600x over previous
#include <cuda_runtime.h>
#include <cuda_fp16.h>
#include <cstdint>

#define OUTD 11008
#define IND  4096
#define BDIM 8192
#define NELEM (OUTD * IND)
#define PPACK (NELEM / 2)
#define XELEM (BDIM * IND)

__device__ __half g_W[NELEM];
__device__ __half g_X[XELEM];

// ---------------------------------------------------------------------------
// Kernel P: fused prep. Blocks [0, XBLK) convert x f32->fp16; the rest
// dequantize packed 4-bit -> fp16 W. Both HBM-bound; one grid keeps HBM full.
// ---------------------------------------------------------------------------
#define XBLK (XELEM / 8 / 256)        // 16384
#define DQBLK (PPACK / 8 / 256)       // 11008

__global__ void __launch_bounds__(256) prep_kernel(
    const float* __restrict__ x,
    const int*   __restrict__ packed,
    const int*   __restrict__ absmax1,
    const float* __restrict__ code1,
    const float* __restrict__ offset1,
    const float* __restrict__ absmax2,
    const float* __restrict__ code2)
{
    if (blockIdx.x < XBLK) {
        int tid = blockIdx.x * 256 + threadIdx.x;
        const float4* x4 = (const float4*)x;
        float4 a = x4[tid * 2];
        float4 b = x4[tid * 2 + 1];
        __half h[8];
        h[0] = __float2half(a.x); h[1] = __float2half(a.y);
        h[2] = __float2half(a.z); h[3] = __float2half(a.w);
        h[4] = __float2half(b.x); h[5] = __float2half(b.y);
        h[6] = __float2half(b.z); h[7] = __float2half(b.w);
        ((uint4*)g_X)[tid] = *(const uint4*)h;
    } else {
        int tid = (blockIdx.x - XBLK) * 256 + threadIdx.x;   // [0, PPACK/8)
        int blk1 = tid >> 2;
        int blk2 = tid >> 4;
        float s   = ((float)absmax1[blk1] / code1[blk1]) * (absmax2[blk2] / code2[blk2]);
        float off = offset1[blk1];
        const int4* p4 = (const int4*)packed;
        int4 p0 = p4[tid * 2];
        int4 p1 = p4[tid * 2 + 1];
        int b[8] = {p0.x, p0.y, p0.z, p0.w, p1.x, p1.y, p1.z, p1.w};
        __half h[16];
#pragma unroll
        for (int j = 0; j < 8; j++) {
            float lo = (float)(b[j] & 15);
            float hi = (float)((b[j] >> 4) & 15);
            h[2 * j]     = __float2half((lo - off) * s);
            h[2 * j + 1] = __float2half((hi - off) * s);
        }
        uint4* w4 = (uint4*)g_W;
        const uint4* hv = (const uint4*)h;
        w4[tid * 2]     = hv[0];
        w4[tid * 2 + 1] = hv[1];
    }
}

// ---------------------------------------------------------------------------
// Kernel 2: HMMA GEMM — champion config (R5 mainloop), with all
// loop-invariant address math hoisted out of the K-tile loop.
// BM=128, BN=128, BK=64; 8 warps 4(M)x2(N); 3-stage ring; 2 CTAs/SM.
// ---------------------------------------------------------------------------
#define BM 128
#define BN 128
#define BK 64
#define STAGES 3
#define KTILES (IND / BK)            // 64
#define STG_BYTES 16384
#define SMEM_TOTAL (2 * STAGES * STG_BYTES)   // 98304

__device__ __forceinline__ unsigned swz(int row, int kc) {
    return (unsigned)(row * 128 + ((kc ^ (row & 7)) << 4));
}
__device__ __forceinline__ void ldm_x4(unsigned* d, unsigned addr) {
    asm volatile("ldmatrix.sync.aligned.m8n8.x4.shared.b16 {%0,%1,%2,%3}, [%4];"
                 : "=r"(d[0]), "=r"(d[1]), "=r"(d[2]), "=r"(d[3]) : "r"(addr));
}
__device__ __forceinline__ void mma16816(float* c, const unsigned* a,
                                         unsigned b0, unsigned b1) {
    asm volatile(
        "mma.sync.aligned.m16n8k16.row.col.f32.f16.f16.f32 "
        "{%0,%1,%2,%3}, {%4,%5,%6,%7}, {%8,%9}, {%0,%1,%2,%3};"
        : "+f"(c[0]), "+f"(c[1]), "+f"(c[2]), "+f"(c[3])
        : "r"(a[0]), "r"(a[1]), "r"(a[2]), "r"(a[3]), "r"(b0), "r"(b1));
}
__device__ __forceinline__ void cp_async16(unsigned saddr, const void* gaddr) {
    asm volatile("cp.async.cg.shared.global [%0], [%1], 16;"
                 :: "r"(saddr), "l"(gaddr));
}
__device__ __forceinline__ void stcs2(float* p, float a, float b) {
    asm volatile("st.global.cs.v2.f32 [%0], {%1, %2};" :: "l"(p), "f"(a), "f"(b)
                 : "memory");
}

__global__ void __launch_bounds__(256, 2) gemm_kernel(float* __restrict__ C)
{
    extern __shared__ char smem[];
    unsigned sA = (unsigned)__cvta_generic_to_shared(smem);
    unsigned sB = sA + STAGES * STG_BYTES;

    const int tid  = threadIdx.x;
    const int lane = tid & 31;
    const int warp = tid >> 5;
    const int wm   = warp >> 1;     // 0..3
    const int wn   = warp & 1;      // 0..1

    const int bn = blockIdx.x;
    const int bm = blockIdx.y;

    const __half* xsrc0 = g_X + (size_t)bm * BM * IND;
    const __half* wsrc0 = g_W + (size_t)bn * BN * IND;

    float acc[2][8][4] = {};

    // ---- loop-invariant ldsm addressing: base addr per (mi/nj), per-kk step
    const int rselA = lane & 15;
    const int cselA = lane >> 4;
    const int rselB = (lane & 7) | ((lane >> 1) & 8);
    const int cselB = (lane >> 3) & 1;

    // a/b ldsm smem offsets within a stage, for each kk (kc = kk*2 + csel)
    unsigned aOff[2][4], bOff[4][4];
#pragma unroll
    for (int mi = 0; mi < 2; mi++) {
        int r = wm * 32 + mi * 16 + rselA;
#pragma unroll
        for (int kk = 0; kk < 4; kk++)
            aOff[mi][kk] = (unsigned)(r * 128 + (((kk * 2 + cselA) ^ (r & 7)) << 4));
    }
#pragma unroll
    for (int nj = 0; nj < 4; nj++) {
        int r = wn * 64 + nj * 16 + rselB;
#pragma unroll
        for (int kk = 0; kk < 4; kk++)
            bOff[nj][kk] = (unsigned)(r * 128 + (((kk * 2 + cselB) ^ (r & 7)) << 4));
    }

    // ---- loop-invariant cp.async addressing ----
    unsigned sOff[4];           // swizzled smem offset within a stage
    size_t   gOff[4];           // element offset within a tile row-block
#pragma unroll
    for (int i = 0; i < 4; i++) {
        int id  = tid + i * 256;
        int row = id >> 3, kc = id & 7;
        sOff[i] = swz(row, kc);
        gOff[i] = (size_t)row * IND + kc * 8;
    }

    auto load_stage = [&](unsigned slotOff, int kt) {
        const __half* xs = xsrc0 + (size_t)kt * BK;
        const __half* ws = wsrc0 + (size_t)kt * BK;
        unsigned aB = sA + slotOff;
        unsigned bB = sB + slotOff;
#pragma unroll
        for (int i = 0; i < 4; i++)
            cp_async16(aB + sOff[i], xs + gOff[i]);
#pragma unroll
        for (int i = 0; i < 4; i++)
            cp_async16(bB + sOff[i], ws + gOff[i]);
    };

    load_stage(0, 0);
    asm volatile("cp.async.commit_group;");
    load_stage(STG_BYTES, 1);
    asm volatile("cp.async.commit_group;");

    unsigned cSlot = 0;                       // (kt % 3) * STG_BYTES, via wrap
    unsigned lSlot = 2 * STG_BYTES;           // ((kt+2) % 3) * STG_BYTES
    for (int kt = 0; kt < KTILES; kt++) {
        asm volatile("cp.async.wait_group 1;");   // stage kt resident
        __syncthreads();                          // all warps done with kt-1

        if (kt + 2 < KTILES) load_stage(lSlot, kt + 2);
        asm volatile("cp.async.commit_group;");
        lSlot = (lSlot == 2 * STG_BYTES) ? 0 : lSlot + STG_BYTES;

        unsigned aBase = sA + cSlot;
        unsigned bBase = sB + cSlot;
        cSlot = (cSlot == 2 * STG_BYTES) ? 0 : cSlot + STG_BYTES;
#pragma unroll
        for (int kk = 0; kk < 4; kk++) {
            unsigned afrag[2][4];
#pragma unroll
            for (int mi = 0; mi < 2; mi++)
                ldm_x4(afrag[mi], aBase + aOff[mi][kk]);
            unsigned bfrag[4][4];
#pragma unroll
            for (int nj = 0; nj < 4; nj++)
                ldm_x4(bfrag[nj], bBase + bOff[nj][kk]);
#pragma unroll
            for (int mi = 0; mi < 2; mi++) {
#pragma unroll
                for (int nj = 0; nj < 4; nj++) {
                    mma16816(acc[mi][2 * nj],     afrag[mi], bfrag[nj][0], bfrag[nj][1]);
                    mma16816(acc[mi][2 * nj + 1], afrag[mi], bfrag[nj][2], bfrag[nj][3]);
                }
            }
        }
    }

    // ---- epilogue: fp16-round, streaming f32 stores (evict-first) ----
    const int r0 = bm * BM + wm * 32 + (lane >> 2);
    const int c0 = bn * BN + wn * 64 + 2 * (lane & 3);
#pragma unroll
    for (int mi = 0; mi < 2; mi++) {
#pragma unroll
        for (int ni = 0; ni < 8; ni++) {
            int r = r0 + mi * 16;
            int c = c0 + ni * 8;
            stcs2(C + (size_t)r * OUTD + c,
                  __half2float(__float2half(acc[mi][ni][0])),
                  __half2float(__float2half(acc[mi][ni][1])));
            stcs2(C + (size_t)(r + 8) * OUTD + c,
                  __half2float(__float2half(acc[mi][ni][2])),
                  __half2float(__float2half(acc[mi][ni][3])));
        }
    }
}

// ---------------------------------------------------------------------------
extern "C" void kernel_launch(void* const* d_in, const int* in_sizes, int n_in,
                              void* d_out, int out_size)
{
    const float* x      = (const float*)d_in[0];
    const int*   packed = (const int*)  d_in[1];
    const int*   am1    = (const int*)  d_in[2];
    const float* c1     = (const float*)d_in[3];
    const float* o1     = (const float*)d_in[4];
    const float* am2    = (const float*)d_in[5];
    const float* c2     = (const float*)d_in[6];
    float* out = (float*)d_out;

    prep_kernel<<<XBLK + DQBLK, 256>>>(x, packed, am1, c1, o1, am2, c2);

    cudaFuncSetAttribute(gemm_kernel,
                         cudaFuncAttributeMaxDynamicSharedMemorySize, SMEM_TOTAL);
    gemm_kernel<<<dim3(OUTD / BN, BDIM / BM), 256, SMEM_TOTAL>>>(out);
}

// round 17
// speedup vs baseline: 1.1252x; 1.0463x over previous
#include <cuda_runtime.h>
#include <cuda_fp16.h>
#include <cstdint>

#define OUTD 11008
#define IND  4096
#define BDIM 8192
#define NELEM (OUTD * IND)
#define PPACK (NELEM / 2)
#define XELEM (BDIM * IND)

__device__ __half g_W[NELEM];
__device__ __half g_X[XELEM];

// ---------------------------------------------------------------------------
// Kernel P: fused prep (verified).
// ---------------------------------------------------------------------------
#define XBLK (XELEM / 8 / 256)        // 16384
#define DQBLK (PPACK / 8 / 256)       // 11008

__global__ void __launch_bounds__(256) prep_kernel(
    const float* __restrict__ x,
    const int*   __restrict__ packed,
    const int*   __restrict__ absmax1,
    const float* __restrict__ code1,
    const float* __restrict__ offset1,
    const float* __restrict__ absmax2,
    const float* __restrict__ code2)
{
    if (blockIdx.x < XBLK) {
        int tid = blockIdx.x * 256 + threadIdx.x;
        const float4* x4 = (const float4*)x;
        float4 a = x4[tid * 2];
        float4 b = x4[tid * 2 + 1];
        __half h[8];
        h[0] = __float2half(a.x); h[1] = __float2half(a.y);
        h[2] = __float2half(a.z); h[3] = __float2half(a.w);
        h[4] = __float2half(b.x); h[5] = __float2half(b.y);
        h[6] = __float2half(b.z); h[7] = __float2half(b.w);
        ((uint4*)g_X)[tid] = *(const uint4*)h;
    } else {
        int tid = (blockIdx.x - XBLK) * 256 + threadIdx.x;   // [0, PPACK/8)
        int blk1 = tid >> 2;
        int blk2 = tid >> 4;
        float s   = ((float)absmax1[blk1] / code1[blk1]) * (absmax2[blk2] / code2[blk2]);
        float off = offset1[blk1];
        const int4* p4 = (const int4*)packed;
        int4 p0 = p4[tid * 2];
        int4 p1 = p4[tid * 2 + 1];
        int b[8] = {p0.x, p0.y, p0.z, p0.w, p1.x, p1.y, p1.z, p1.w};
        __half h[16];
#pragma unroll
        for (int j = 0; j < 8; j++) {
            float lo = (float)(b[j] & 15);
            float hi = (float)((b[j] >> 4) & 15);
            h[2 * j]     = __float2half((lo - off) * s);
            h[2 * j + 1] = __float2half((hi - off) * s);
        }
        uint4* w4 = (uint4*)g_W;
        const uint4* hv = (const uint4*)h;
        w4[tid * 2]     = hv[0];
        w4[tid * 2 + 1] = hv[1];
    }
}

// ---------------------------------------------------------------------------
// Kernel 2: HMMA GEMM — champion config; kt-loop unrolled x3 so stage slots
// are compile-time immediates (LDSM [reg+imm], zero per-ldsm address adds).
// BM=128, BN=128, BK=64; 8 warps 4(M)x2(N); 3-stage ring; 2 CTAs/SM.
// ---------------------------------------------------------------------------
#define BM 128
#define BN 128
#define BK 64
#define STAGES 3
#define KTILES (IND / BK)            // 64
#define STG_BYTES 16384
#define SMEM_TOTAL (2 * STAGES * STG_BYTES)   // 98304

__device__ __forceinline__ unsigned swz(int row, int kc) {
    return (unsigned)(row * 128 + ((kc ^ (row & 7)) << 4));
}
template<int IMM>
__device__ __forceinline__ void ldm_x4i(unsigned* d, unsigned addr) {
    asm volatile("ldmatrix.sync.aligned.m8n8.x4.shared.b16 {%0,%1,%2,%3}, [%4+%5];"
                 : "=r"(d[0]), "=r"(d[1]), "=r"(d[2]), "=r"(d[3])
                 : "r"(addr), "n"(IMM));
}
__device__ __forceinline__ void mma16816(float* c, const unsigned* a,
                                         unsigned b0, unsigned b1) {
    asm volatile(
        "mma.sync.aligned.m16n8k16.row.col.f32.f16.f16.f32 "
        "{%0,%1,%2,%3}, {%4,%5,%6,%7}, {%8,%9}, {%0,%1,%2,%3};"
        : "+f"(c[0]), "+f"(c[1]), "+f"(c[2]), "+f"(c[3])
        : "r"(a[0]), "r"(a[1]), "r"(a[2]), "r"(a[3]), "r"(b0), "r"(b1));
}
__device__ __forceinline__ void cp_async16(unsigned saddr, const void* gaddr) {
    asm volatile("cp.async.cg.shared.global [%0], [%1], 16;"
                 :: "r"(saddr), "l"(gaddr));
}
__device__ __forceinline__ void stcs2(float* p, float a, float b) {
    asm volatile("st.global.cs.v2.f32 [%0], {%1, %2};" :: "l"(p), "f"(a), "f"(b)
                 : "memory");
}

__global__ void __launch_bounds__(256, 2) gemm_kernel(float* __restrict__ C)
{
    extern __shared__ char smem[];
    unsigned sA = (unsigned)__cvta_generic_to_shared(smem);
    unsigned sB = sA + STAGES * STG_BYTES;

    const int tid  = threadIdx.x;
    const int lane = tid & 31;
    const int warp = tid >> 5;
    const int wm   = warp >> 1;     // 0..3
    const int wn   = warp & 1;      // 0..1

    const int bn = blockIdx.x;
    const int bm = blockIdx.y;

    const __half* xsrc0 = g_X + (size_t)bm * BM * IND;
    const __half* wsrc0 = g_W + (size_t)bn * BN * IND;

    float acc[2][8][4] = {};

    const int rselA = lane & 15;
    const int cselA = lane >> 4;
    const int rselB = (lane & 7) | ((lane >> 1) & 8);
    const int cselB = (lane >> 3) & 1;

    // LDSM absolute base addresses (slot 0); other slots via [reg+imm]
    unsigned aAddr[2][4], bAddr[4][4];
#pragma unroll
    for (int mi = 0; mi < 2; mi++) {
        int r = wm * 32 + mi * 16 + rselA;
#pragma unroll
        for (int kk = 0; kk < 4; kk++)
            aAddr[mi][kk] = sA + (unsigned)(r * 128 + (((kk * 2 + cselA) ^ (r & 7)) << 4));
    }
#pragma unroll
    for (int nj = 0; nj < 4; nj++) {
        int r = wn * 64 + nj * 16 + rselB;
#pragma unroll
        for (int kk = 0; kk < 4; kk++)
            bAddr[nj][kk] = sB + (unsigned)(r * 128 + (((kk * 2 + cselB) ^ (r & 7)) << 4));
    }

    // cp.async addressing (loop-invariant)
    unsigned sOff[4];
    size_t   gOff[4];
#pragma unroll
    for (int i = 0; i < 4; i++) {
        int id  = tid + i * 256;
        int row = id >> 3, kc = id & 7;
        sOff[i] = swz(row, kc);
        gOff[i] = (size_t)row * IND + kc * 8;
    }

    auto load_stage = [&](unsigned slotOff, int kt) {
        const __half* xs = xsrc0 + (size_t)kt * BK;
        const __half* ws = wsrc0 + (size_t)kt * BK;
        unsigned aB = sA + slotOff;
        unsigned bB = sB + slotOff;
#pragma unroll
        for (int i = 0; i < 4; i++)
            cp_async16(aB + sOff[i], xs + gOff[i]);
#pragma unroll
        for (int i = 0; i < 4; i++)
            cp_async16(bB + sOff[i], ws + gOff[i]);
    };

#define COMPUTE_TILE(CS)                                                      \
    do {                                                                      \
        _Pragma("unroll")                                                     \
        for (int kk = 0; kk < 4; kk++) {                                      \
            unsigned afrag[2][4];                                             \
            ldm_x4i<(CS) * STG_BYTES>(afrag[0], aAddr[0][kk]);                \
            ldm_x4i<(CS) * STG_BYTES>(afrag[1], aAddr[1][kk]);                \
            unsigned bfrag[4][4];                                             \
            _Pragma("unroll")                                                 \
            for (int nj = 0; nj < 4; nj++)                                    \
                ldm_x4i<(CS) * STG_BYTES>(bfrag[nj], bAddr[nj][kk]);          \
            _Pragma("unroll")                                                 \
            for (int mi = 0; mi < 2; mi++) {                                  \
                _Pragma("unroll")                                             \
                for (int nj = 0; nj < 4; nj++) {                              \
                    mma16816(acc[mi][2 * nj],     afrag[mi],                  \
                             bfrag[nj][0], bfrag[nj][1]);                     \
                    mma16816(acc[mi][2 * nj + 1], afrag[mi],                  \
                             bfrag[nj][2], bfrag[nj][3]);                     \
                }                                                             \
            }                                                                 \
        }                                                                     \
    } while (0)

#define STEP(CS, LS, KT)                                                      \
    do {                                                                      \
        asm volatile("cp.async.wait_group 1;");                               \
        __syncthreads();                                                      \
        if ((KT) + 2 < KTILES) load_stage((LS) * STG_BYTES, (KT) + 2);        \
        asm volatile("cp.async.commit_group;");                               \
        COMPUTE_TILE(CS);                                                     \
    } while (0)

    load_stage(0, 0);
    asm volatile("cp.async.commit_group;");
    load_stage(STG_BYTES, 1);
    asm volatile("cp.async.commit_group;");

    for (int kt0 = 0; kt0 < 63; kt0 += 3) {      // 21 unrolled triples
        STEP(0, 2, kt0);
        STEP(1, 0, kt0 + 1);
        STEP(2, 1, kt0 + 2);
    }
    // tail: kt = 63, slot 0, no further loads
    asm volatile("cp.async.wait_group 1;");
    __syncthreads();
    COMPUTE_TILE(0);

    // ---- epilogue: fp16-round, streaming f32 stores (evict-first) ----
    const int r0 = bm * BM + wm * 32 + (lane >> 2);
    const int c0 = bn * BN + wn * 64 + 2 * (lane & 3);
#pragma unroll
    for (int mi = 0; mi < 2; mi++) {
#pragma unroll
        for (int ni = 0; ni < 8; ni++) {
            int r = r0 + mi * 16;
            int c = c0 + ni * 8;
            stcs2(C + (size_t)r * OUTD + c,
                  __half2float(__float2half(acc[mi][ni][0])),
                  __half2float(__float2half(acc[mi][ni][1])));
            stcs2(C + (size_t)(r + 8) * OUTD + c,
                  __half2float(__float2half(acc[mi][ni][2])),
                  __half2float(__float2half(acc[mi][ni][3])));
        }
    }
}

// ---------------------------------------------------------------------------
extern "C" void kernel_launch(void* const* d_in, const int* in_sizes, int n_in,
                              void* d_out, int out_size)
{
    const float* x      = (const float*)d_in[0];
    const int*   packed = (const int*)  d_in[1];
    const int*   am1    = (const int*)  d_in[2];
    const float* c1     = (const float*)d_in[3];
    const float* o1     = (const float*)d_in[4];
    const float* am2    = (const float*)d_in[5];
    const float* c2     = (const float*)d_in[6];
    float* out = (float*)d_out;

    prep_kernel<<<XBLK + DQBLK, 256>>>(x, packed, am1, c1, o1, am2, c2);

    cudaFuncSetAttribute(gemm_kernel,
                         cudaFuncAttributeMaxDynamicSharedMemorySize, SMEM_TOTAL);
    gemm_kernel<<<dim3(OUTD / BN, BDIM / BM), 256, SMEM_TOTAL>>>(out);
}